// round 2
// baseline (speedup 1.0000x reference)
#include <cuda_runtime.h>
#include <cuda_bf16.h>

#define K_ 16
#define P_ 27000
#define S_ 16
#define NODES 31

// M_OPS table (16 ops x 4 coefficients)
__constant__ float c_MOPS[64] = {
    0,0,0,0,   0,0,0,1,   0,1,0,-1,  0,1,0,0,
    0,0,1,-1,  0,0,1,0,   0,1,1,-2,  0,1,1,-1,
    1,-1,-1,1, 1,-1,-1,2, 1,0,-1,0,  1,0,-1,1,
    1,-1,0,0,  1,-1,0,1,  1,0,0,-1,  1,0,0,0
};

// Precomputed per-launch scratch (allowed: __device__ globals, no allocation)
__device__ float4 g_coef[K_ * NODES];   // [k][node] -> (c0,c1,c2,c3)
__device__ int    g_lin[2 * K_ * S_];   // [0..255]=lin_a[k][s], [256..511]=lin_b[k][s]

// ---------------------------------------------------------------------------
// Prep kernel: reconstruct base linear offsets from idx_*[k, p=0, s, :] and
// compute softmax(w) @ M_OPS coefficients for all 31 tree nodes x 16 k.
// idx layout: (K, P, S, 4) int32, components (h, w, d, c).
// x layout: (B, C=3, 32, 32, 32): strides b=98304, c=32768, h=1024, w=32, d=1.
// ---------------------------------------------------------------------------
__global__ void prep_kernel(const int* __restrict__ ia, const int* __restrict__ ib,
                            const float* __restrict__ w0, const float* __restrict__ w1,
                            const float* __restrict__ w2, const float* __restrict__ w3,
                            const float* __restrict__ w4)
{
    int t = threadIdx.x;

    if (t < 512) {
        const int* src = (t < 256) ? ia : ib;
        int u = t & 255;
        int k = u >> 4;
        int s = u & 15;
        // element [k][0][s][comp] at ((k*P + 0)*S + s)*4 + comp
        long long base = ((long long)k * P_ * S_ + s) * 4;
        int h = src[base + 0];
        int w = src[base + 1];
        int d = src[base + 2];
        int c = src[base + 3];
        g_lin[t] = c * 32768 + h * 1024 + w * 32 + d;
    }

    if (t < K_ * NODES) {
        int k = t / NODES;
        int j = t % NODES;
        const float* wp;
        int n;
        if      (j < 16) { wp = w0; n = j;      }
        else if (j < 24) { wp = w1; n = j - 16; }
        else if (j < 28) { wp = w2; n = j - 24; }
        else if (j < 30) { wp = w3; n = j - 28; }
        else             { wp = w4; n = 0;      }
        const float* row = wp + (n * K_ + k) * 16;

        float m = row[0];
        #pragma unroll
        for (int o = 1; o < 16; o++) m = fmaxf(m, row[o]);
        float e[16];
        float sum = 0.f;
        #pragma unroll
        for (int o = 0; o < 16; o++) { e[o] = expf(row[o] - m); sum += e[o]; }
        float inv = 1.0f / sum;
        float c0 = 0.f, c1 = 0.f, c2 = 0.f, c3 = 0.f;
        #pragma unroll
        for (int o = 0; o < 16; o++) {
            float p = e[o] * inv;
            c0 += p * c_MOPS[o * 4 + 0];
            c1 += p * c_MOPS[o * 4 + 1];
            c2 += p * c_MOPS[o * 4 + 2];
            c3 += p * c_MOPS[o * 4 + 3];
        }
        g_coef[k * NODES + j] = make_float4(c0, c1, c2, c3);
    }
}

// ---------------------------------------------------------------------------
// Main kernel: one thread per output voxel p, block = 256 p's,
// grid = (ceil(P/256), K, B). 32 gathers + 31 bilinear tree ops per thread.
// Consecutive threads hit consecutive d -> near-coalesced, L1-resident x.
// ---------------------------------------------------------------------------
__global__ __launch_bounds__(256)
void logicconv_kernel(const float* __restrict__ x, float* __restrict__ out)
{
    __shared__ float4 s_coef[NODES];
    __shared__ int s_la[S_];
    __shared__ int s_lb[S_];

    const int k = blockIdx.y;
    const int b = blockIdx.z;
    const int t = threadIdx.x;

    if (t < NODES) s_coef[t] = g_coef[k * NODES + t];
    if (t >= 32 && t < 48)  s_la[t - 32] = g_lin[k * S_ + (t - 32)];
    if (t >= 64 && t < 80)  s_lb[t - 64] = g_lin[256 + k * S_ + (t - 64)];
    __syncthreads();

    const int p = blockIdx.x * 256 + t;
    if (p >= P_) return;

    const int pd  = p % 30;
    const int tmp = p / 30;
    const int pw  = tmp % 30;
    const int ph  = tmp / 30;
    const int plin = ph * 1024 + pw * 32 + pd;

    const float* __restrict__ xb = x + b * 98304 + plin;

    float v[S_];
    #pragma unroll
    for (int s = 0; s < S_; s++) {
        float a  = __ldg(xb + s_la[s]);
        float bb = __ldg(xb + s_lb[s]);
        float4 c = s_coef[s];
        v[s] = c.x + c.y * a + c.z * bb + c.w * (a * bb);
    }
    #pragma unroll
    for (int n = 0; n < 8; n++) {
        float4 c = s_coef[16 + n];
        float a = v[2 * n], bb = v[2 * n + 1];
        v[n] = c.x + c.y * a + c.z * bb + c.w * (a * bb);
    }
    #pragma unroll
    for (int n = 0; n < 4; n++) {
        float4 c = s_coef[24 + n];
        float a = v[2 * n], bb = v[2 * n + 1];
        v[n] = c.x + c.y * a + c.z * bb + c.w * (a * bb);
    }
    #pragma unroll
    for (int n = 0; n < 2; n++) {
        float4 c = s_coef[28 + n];
        float a = v[2 * n], bb = v[2 * n + 1];
        v[n] = c.x + c.y * a + c.z * bb + c.w * (a * bb);
    }
    {
        float4 c = s_coef[30];
        float a = v[0], bb = v[1];
        v[0] = c.x + c.y * a + c.z * bb + c.w * (a * bb);
    }

    out[(b * K_ + k) * P_ + p] = v[0];
}

// ---------------------------------------------------------------------------
// Launch: identify inputs by element count (all distinct except idx_a/idx_b,
// which retain their relative order in any plausible metadata ordering).
// ---------------------------------------------------------------------------
extern "C" void kernel_launch(void* const* d_in, const int* in_sizes, int n_in,
                              void* d_out, int out_size)
{
    const float* x  = nullptr;
    const int*   ia = nullptr;
    const int*   ib = nullptr;
    const float* w0 = nullptr;
    const float* w1 = nullptr;
    const float* w2 = nullptr;
    const float* w3 = nullptr;
    const float* w4 = nullptr;

    for (int i = 0; i < n_in; i++) {
        int sz = in_sizes[i];
        switch (sz) {
            case 393216:   x  = (const float*)d_in[i]; break;          // 4*3*32^3
            case 27648000:                                              // K*P*S*4
                if (!ia) ia = (const int*)d_in[i];
                else     ib = (const int*)d_in[i];
                break;
            case 4096:     w0 = (const float*)d_in[i]; break;          // 16*16*16
            case 2048:     w1 = (const float*)d_in[i]; break;          // 8*16*16
            case 1024:     w2 = (const float*)d_in[i]; break;          // 4*16*16
            case 512:      w3 = (const float*)d_in[i]; break;          // 2*16*16
            case 256:      w4 = (const float*)d_in[i]; break;          // 1*16*16
            default: break;
        }
    }

    prep_kernel<<<1, 512>>>(ia, ib, w0, w1, w2, w3, w4);

    dim3 grid((P_ + 255) / 256, K_, 4);
    logicconv_kernel<<<grid, 256>>>(x, (float*)d_out);
}

// round 4
// speedup vs baseline: 1.0103x; 1.0103x over previous
#include <cuda_runtime.h>
#include <cuda_bf16.h>

#define K_ 16
#define P_ 27000

// Shared tile geometry: [c=3][h=4][w=17][d=32]
#define TH_OUT 2
#define TW_OUT 15
#define TH 4
#define TW 17
#define TD 32
#define H_STRIDE (TW * TD)         // 544
#define C_STRIDE (TH * H_STRIDE)   // 2176
#define TILE_ELEMS (3 * C_STRIDE)  // 6528 floats = 26112 B

// M_OPS table (16 ops x 4 coefficients)
__constant__ float c_MOPS[64] = {
    0,0,0,0,   0,0,0,1,   0,1,0,-1,  0,1,0,0,
    0,0,1,-1,  0,0,1,0,   0,1,1,-2,  0,1,1,-1,
    1,-1,-1,1, 1,-1,-1,2, 1,0,-1,0,  1,0,-1,1,
    1,-1,0,0,  1,-1,0,1,  1,0,0,-1,  1,0,0,0
};

// node op: c0 + c1*a + c2*b + c3*a*b = fma(b, fma(c3,a,c2), fma(c1,a,c0))
__device__ __forceinline__ float node_op(float4 c, float a, float b) {
    return fmaf(b, fmaf(c.w, a, c.z), fmaf(c.y, a, c.x));
}

__global__ __launch_bounds__(256)
void logic_fused(const float* __restrict__ x,
                 const int* __restrict__ ia, const int* __restrict__ ib,
                 const float* __restrict__ w0, const float* __restrict__ w1,
                 const float* __restrict__ w2, const float* __restrict__ w3,
                 const float* __restrict__ w4,
                 float* __restrict__ out)
{
    __shared__ float  s_tile[TILE_ELEMS];
    __shared__ float4 s_coef[31];
    __shared__ int2   s_lin[16];   // (.x = lin_a, .y = lin_b) in tile units

    const int tile = blockIdx.x;           // 0..29
    const int k    = blockIdx.y;           // 0..15
    const int b    = blockIdx.z;           // 0..3
    const int h0   = (tile >> 1) * TH_OUT; // 0,2,...,28
    const int w0_  = (tile & 1) * TW_OUT;  // 0 or 15
    const int t    = threadIdx.x;

    // ---- per-block prep: tree coefficients (threads 0..30) ----
    if (t < 31) {
        const float* wp; int n;
        if      (t < 16) { wp = w0; n = t;      }
        else if (t < 24) { wp = w1; n = t - 16; }
        else if (t < 28) { wp = w2; n = t - 24; }
        else if (t < 30) { wp = w3; n = t - 28; }
        else             { wp = w4; n = 0;      }
        const float* row = wp + (n * K_ + k) * 16;
        float r[16];
        float m = -1e30f;
        #pragma unroll
        for (int o = 0; o < 16; o++) { r[o] = row[o]; m = fmaxf(m, r[o]); }
        float sum = 0.f;
        #pragma unroll
        for (int o = 0; o < 16; o++) { r[o] = __expf(r[o] - m); sum += r[o]; }
        float inv = 1.0f / sum;
        float c0 = 0.f, c1 = 0.f, c2 = 0.f, c3 = 0.f;
        #pragma unroll
        for (int o = 0; o < 16; o++) {
            float p = r[o] * inv;
            c0 = fmaf(p, c_MOPS[4*o + 0], c0);
            c1 = fmaf(p, c_MOPS[4*o + 1], c1);
            c2 = fmaf(p, c_MOPS[4*o + 2], c2);
            c3 = fmaf(p, c_MOPS[4*o + 3], c3);
        }
        s_coef[t] = make_float4(c0, c1, c2, c3);
    }
    // ---- per-block prep: leaf offsets from idx[k][p=0][s] (threads 32..63) ----
    if (t >= 32 && t < 64) {
        int u = t - 32;                      // 0..31
        const int* src = (u < 16) ? ia : ib;
        int s = u & 15;
        int base = (k * P_ * 16 + s) * 4;    // fits in int (max ~26M)
        int h = src[base + 0];
        int w = src[base + 1];
        int d = src[base + 2];
        int c = src[base + 3];
        int lin = c * C_STRIDE + h * H_STRIDE + w * TD + d;
        if (u < 16) s_lin[s].x = lin;
        else        s_lin[s].y = lin;
    }

    // ---- cooperative tile load (vectorized, coalesced) ----
    const float* xb = x + b * 98304;
    #pragma unroll 2
    for (int i = t; i < TILE_ELEMS / 4; i += 256) {   // 1632 float4
        int e  = i * 4;
        int c  = e / C_STRIDE;
        int r  = e - c * C_STRIDE;
        int h  = r / H_STRIDE;
        int r2 = r - h * H_STRIDE;
        int w  = r2 >> 5;
        int d  = r2 & 31;
        float4 v = *reinterpret_cast<const float4*>(
            xb + ((c * 32 + (h0 + h)) * 32 + (w0_ + w)) * 32 + d);
        *reinterpret_cast<float4*>(s_tile + e) = v;
    }
    __syncthreads();

    // ---- compute: 4 outputs per thread (900 outputs / block) ----
    // local output id q in [0,900): lh = q/450, lw = (q%450)/30, ld = q%30
    int  qv[4];
    int  bases[4];
    #pragma unroll
    for (int o = 0; o < 4; o++) {
        int qq = t + o * 256;
        qv[o] = qq;
        int qc = min(qq, 899);               // clamp: inactive lanes compute garbage, don't store
        int lh = qc / 450;
        int r  = qc - lh * 450;
        int lw = r / 30;
        int ld = r - lw * 30;
        bases[o] = lh * H_STRIDE + lw * TD + ld;
    }

    float v[4][16];
    #pragma unroll
    for (int s = 0; s < 16; s++) {
        int2   lab = s_lin[s];
        float4 c   = s_coef[s];
        #pragma unroll
        for (int o = 0; o < 4; o++) {
            float a  = s_tile[bases[o] + lab.x];
            float bb = s_tile[bases[o] + lab.y];
            v[o][s] = node_op(c, a, bb);
        }
    }
    #pragma unroll
    for (int n = 0; n < 8; n++) {
        float4 c = s_coef[16 + n];
        #pragma unroll
        for (int o = 0; o < 4; o++)
            v[o][n] = node_op(c, v[o][2*n], v[o][2*n + 1]);
    }
    #pragma unroll
    for (int n = 0; n < 4; n++) {
        float4 c = s_coef[24 + n];
        #pragma unroll
        for (int o = 0; o < 4; o++)
            v[o][n] = node_op(c, v[o][2*n], v[o][2*n + 1]);
    }
    #pragma unroll
    for (int n = 0; n < 2; n++) {
        float4 c = s_coef[28 + n];
        #pragma unroll
        for (int o = 0; o < 4; o++)
            v[o][n] = node_op(c, v[o][2*n], v[o][2*n + 1]);
    }
    {
        float4 c = s_coef[30];
        #pragma unroll
        for (int o = 0; o < 4; o++)
            v[o][0] = node_op(c, v[o][0], v[o][1]);
    }

    // ---- store ----
    float* op = out + (b * K_ + k) * P_;
    const int pbase = h0 * 900 + w0_ * 30;
    #pragma unroll
    for (int o = 0; o < 4; o++) {
        int qq = qv[o];
        if (qq < 900) {
            int lh = qq / 450;
            int r  = qq - lh * 450;
            int lw = r / 30;
            int ld = r - lw * 30;
            op[pbase + lh * 900 + lw * 30 + ld] = v[o][0];
        }
    }
}

extern "C" void kernel_launch(void* const* d_in, const int* in_sizes, int n_in,
                              void* d_out, int out_size)
{
    const float* x  = nullptr;
    const int*   ia = nullptr;
    const int*   ib = nullptr;
    const float* w0 = nullptr;
    const float* w1 = nullptr;
    const float* w2 = nullptr;
    const float* w3 = nullptr;
    const float* w4 = nullptr;

    for (int i = 0; i < n_in; i++) {
        int sz = in_sizes[i];
        switch (sz) {
            case 393216:   x  = (const float*)d_in[i]; break;   // 4*3*32^3
            case 27648000:                                      // K*P*S*4
                if (!ia) ia = (const int*)d_in[i];
                else     ib = (const int*)d_in[i];
                break;
            case 4096:     w0 = (const float*)d_in[i]; break;
            case 2048:     w1 = (const float*)d_in[i]; break;
            case 1024:     w2 = (const float*)d_in[i]; break;
            case 512:      w3 = (const float*)d_in[i]; break;
            case 256:      w4 = (const float*)d_in[i]; break;
            default: break;
        }
    }

    dim3 grid(30, K_, 4);
    logic_fused<<<grid, 256>>>(x, ia, ib, w0, w1, w2, w3, w4, (float*)d_out);
}

// round 6
// speedup vs baseline: 1.5032x; 1.4879x over previous
#include <cuda_runtime.h>
#include <cuda_bf16.h>

#define K_ 16
#define P_ 27000

// Tile: x[b, c=0..2, h0:h0+3, 0:32, 0:32] -> s_tile[c][h][w][d]
// strides: c=3072, h=1024, w=32, d=1  (all shift/add addressable)
#define TILE_ELEMS (3 * 3072)   // 9216 floats = 36 KB

__constant__ float c_MOPS[64] = {
    0,0,0,0,   0,0,0,1,   0,1,0,-1,  0,1,0,0,
    0,0,1,-1,  0,0,1,0,   0,1,1,-2,  0,1,1,-1,
    1,-1,-1,1, 1,-1,-1,2, 1,0,-1,0,  1,0,-1,1,
    1,-1,0,0,  1,-1,0,1,  1,0,0,-1,  1,0,0,0
};

// c0 + c1*a + c2*b + c3*a*b = fma(b, fma(c3,a,c2), fma(c1,a,c0))
__device__ __forceinline__ float node_op(float4 c, float a, float b) {
    return fmaf(b, fmaf(c.w, a, c.z), fmaf(c.y, a, c.x));
}

__global__ __launch_bounds__(256, 4)
void logic_fused(const float* __restrict__ x,
                 const int* __restrict__ ia, const int* __restrict__ ib,
                 const float* __restrict__ w0, const float* __restrict__ w1,
                 const float* __restrict__ w2, const float* __restrict__ w3,
                 const float* __restrict__ w4,
                 float* __restrict__ out)
{
    __shared__ float  s_tile[TILE_ELEMS];
    __shared__ float4 s_coef[31];
    __shared__ int2   s_lin[16];

    const int h0 = blockIdx.x;   // 0..29 (output h row)
    const int k  = blockIdx.y;
    const int b  = blockIdx.z;
    const int t  = threadIdx.x;

    // ---- prep: tree coefficients (threads 0..30) ----
    if (t < 31) {
        const float* wp; int n;
        if      (t < 16) { wp = w0; n = t;      }
        else if (t < 24) { wp = w1; n = t - 16; }
        else if (t < 28) { wp = w2; n = t - 24; }
        else if (t < 30) { wp = w3; n = t - 28; }
        else             { wp = w4; n = 0;      }
        const float* row = wp + (n * K_ + k) * 16;
        float r[16];
        float m = -1e30f;
        #pragma unroll
        for (int o = 0; o < 16; o++) { r[o] = row[o]; m = fmaxf(m, r[o]); }
        float sum = 0.f;
        #pragma unroll
        for (int o = 0; o < 16; o++) { r[o] = __expf(r[o] - m); sum += r[o]; }
        float inv = 1.0f / sum;
        float c0 = 0.f, c1 = 0.f, c2 = 0.f, c3 = 0.f;
        #pragma unroll
        for (int o = 0; o < 16; o++) {
            float p = r[o] * inv;
            c0 = fmaf(p, c_MOPS[4*o + 0], c0);
            c1 = fmaf(p, c_MOPS[4*o + 1], c1);
            c2 = fmaf(p, c_MOPS[4*o + 2], c2);
            c3 = fmaf(p, c_MOPS[4*o + 3], c3);
        }
        s_coef[t] = make_float4(c0, c1, c2, c3);
    }
    // ---- prep: leaf offsets from idx[k][p=0][s] (threads 32..63) ----
    if (t >= 32 && t < 64) {
        int u = t - 32;
        const int* src = (u < 16) ? ia : ib;
        int s = u & 15;
        int base = (k * P_ * 16 + s) * 4;
        int h = src[base + 0];
        int w = src[base + 1];
        int d = src[base + 2];
        int c = src[base + 3];
        int lin = c * 3072 + h * 1024 + w * 32 + d;   // tile-space offset
        if (u < 16) s_lin[s].x = lin;
        else        s_lin[s].y = lin;
    }

    // ---- tile load: 3 contiguous 3072-float slabs, pure float4 copies ----
    {
        const float* src = x + b * 98304 + h0 * 1024;   // x[b,0,h0,0,0]
        #pragma unroll
        for (int c = 0; c < 3; c++) {
            #pragma unroll
            for (int j = 0; j < 3; j++) {
                int idx = j * 256 + t;                  // float4 index, 0..767
                float4 v = *reinterpret_cast<const float4*>(src + c * 32768 + idx * 4);
                *reinterpret_cast<float4*>(s_tile + c * 3072 + idx * 4) = v;
            }
        }
    }
    __syncthreads();

    // ---- compute: lane = ld, row lw = warp + 8*o, 4 rows per thread ----
    const int lane = t & 31;
    const int warp = t >> 5;
    const int ld   = min(lane, 29);        // lanes 30,31 broadcast lane 29

    int bases[4];
    #pragma unroll
    for (int o = 0; o < 4; o++) {
        int lw = min(warp + 8 * o, 29);    // warps 6,7 @ o=3 clamp (no store)
        bases[o] = lw * 32 + ld;
    }

    // tournament tree: stream level-1/2 reductions to cap live registers
    float t2[4][4];
    #pragma unroll
    for (int n2 = 0; n2 < 4; n2++) {
        float p[4], q[4];
        {
            int s = 4 * n2;
            int2   la = s_lin[s],     lb = s_lin[s + 1];
            float4 ca = s_coef[s],    cb = s_coef[s + 1];
            float4 cn = s_coef[16 + 2 * n2];
            #pragma unroll
            for (int o = 0; o < 4; o++) {
                float a0 = s_tile[bases[o] + la.x];
                float b0 = s_tile[bases[o] + la.y];
                float a1 = s_tile[bases[o] + lb.x];
                float b1 = s_tile[bases[o] + lb.y];
                p[o] = node_op(cn, node_op(ca, a0, b0), node_op(cb, a1, b1));
            }
        }
        {
            int s = 4 * n2 + 2;
            int2   la = s_lin[s],     lb = s_lin[s + 1];
            float4 ca = s_coef[s],    cb = s_coef[s + 1];
            float4 cn = s_coef[16 + 2 * n2 + 1];
            #pragma unroll
            for (int o = 0; o < 4; o++) {
                float a0 = s_tile[bases[o] + la.x];
                float b0 = s_tile[bases[o] + la.y];
                float a1 = s_tile[bases[o] + lb.x];
                float b1 = s_tile[bases[o] + lb.y];
                q[o] = node_op(cn, node_op(ca, a0, b0), node_op(cb, a1, b1));
            }
        }
        float4 c2 = s_coef[24 + n2];
        #pragma unroll
        for (int o = 0; o < 4; o++)
            t2[n2][o] = node_op(c2, p[o], q[o]);
    }

    const float4 c3a = s_coef[28], c3b = s_coef[29], c4 = s_coef[30];
    float res[4];
    #pragma unroll
    for (int o = 0; o < 4; o++)
        res[o] = node_op(c4, node_op(c3a, t2[0][o], t2[1][o]),
                             node_op(c3b, t2[2][o], t2[3][o]));

    // ---- store: out[b,k, h0, lw, ld], coalesced over lane ----
    if (lane < 30) {
        float* op = out + (b * K_ + k) * P_ + h0 * 900 + lane;
        #pragma unroll
        for (int o = 0; o < 4; o++) {
            int lw = warp + 8 * o;
            if (lw < 30) op[lw * 30] = res[o];
        }
    }
}

extern "C" void kernel_launch(void* const* d_in, const int* in_sizes, int n_in,
                              void* d_out, int out_size)
{
    const float* x  = nullptr;
    const int*   ia = nullptr;
    const int*   ib = nullptr;
    const float* w0 = nullptr;
    const float* w1 = nullptr;
    const float* w2 = nullptr;
    const float* w3 = nullptr;
    const float* w4 = nullptr;

    for (int i = 0; i < n_in; i++) {
        int sz = in_sizes[i];
        switch (sz) {
            case 393216:   x  = (const float*)d_in[i]; break;   // 4*3*32^3
            case 27648000:                                      // K*P*S*4
                if (!ia) ia = (const int*)d_in[i];
                else     ib = (const int*)d_in[i];
                break;
            case 4096:     w0 = (const float*)d_in[i]; break;
            case 2048:     w1 = (const float*)d_in[i]; break;
            case 1024:     w2 = (const float*)d_in[i]; break;
            case 512:      w3 = (const float*)d_in[i]; break;
            case 256:      w4 = (const float*)d_in[i]; break;
            default: break;
        }
    }

    dim3 grid(30, K_, 4);
    logic_fused<<<grid, 256>>>(x, ia, ib, w0, w1, w2, w3, w4, (float*)d_out);
}